// round 7
// baseline (speedup 1.0000x reference)
#include <cuda_runtime.h>
#include <cstdint>

#define D       128
#define NROWS   20000
#define NPAD    20480
#define NA      1024
#define TA      16        // anchors per CTA (halves chunk re-read traffic)
#define CROWS   1024      // rows per CTA chunk
#define NCHUNK  20
#define KSEL    8
#define KTOP    10
#define GAMMA   1.0f
#define SCALE   25.4f     // int8 quant scale, selection-only
#define QB      79        // quant row-blocks (79*256 >= 20000)

typedef unsigned int uint;

// Static device scratch (allocation-free rule: __device__ globals only)
__device__ __align__(16) uint g_qT[2][D / 4][NPAD];     // transposed packed DB
__device__ __align__(16) uint g_anchq[2][NA][D / 4];    // packed quantized anchors
__device__ __align__(16) float g_anch[2][NA][D];        // fp32 anchors
__device__ float g_Dm[NA];                              // positive dist + gamma
__device__ int   g_candi[2][NA][NCHUNK * KSEL];         // candidate row indices
__device__ float g_partial[2 * NA];                     // per-anchor loss

// Fused SAD-accumulate: acc += sum_bytes(|s8(a) - s8(b)|)  (single SASS op)
__device__ __forceinline__ void sad4(uint& acc, uint a, uint b) {
    asm("vabsdiff4.u32.s32.s32.add %0, %1, %2, %0;" : "+r"(acc) : "r"(a), "r"(b));
}

__device__ __forceinline__ uint quant_pack4(float4 f) {
    int x = __float2int_rn(fminf(fmaxf(f.x * SCALE, -127.f), 127.f));
    int y = __float2int_rn(fminf(fmaxf(f.y * SCALE, -127.f), 127.f));
    int z = __float2int_rn(fminf(fmaxf(f.z * SCALE, -127.f), 127.f));
    int w = __float2int_rn(fminf(fmaxf(f.w * SCALE, -127.f), 127.f));
    return (uint)(x & 255) | ((uint)(y & 255) << 8) |
           ((uint)(z & 255) << 16) | ((uint)(w & 255) << 24);
}

// ---------------------------------------------------------------------------
// Prep: quantize+transpose DBs (blocks 0..2*QB-1) and gather anchors
// (blocks 2*QB.., 2 anchors per block).
// ---------------------------------------------------------------------------
__global__ void k_prep(const float* __restrict__ out1,
                       const float* __restrict__ out2,
                       const int* __restrict__ an1,
                       const int* __restrict__ an2) {
    int b = blockIdx.x;
    int tid = threadIdx.x;
    if (b < 2 * QB) {
        int side = (b >= QB);
        const float* src = side ? out1 : out2;
        int row = (side ? b - QB : b) * 256 + tid;
        if (row >= NROWS) return;
        const float4* s = (const float4*)(src + (size_t)row * D);
        #pragma unroll
        for (int j = 0; j < D / 4; j++)
            g_qT[side][j][row] = quant_pack4(s[j]);
        return;
    }
    // gather: 2 anchors per block, 128 threads each
    int i = (b - 2 * QB) * 2 + (tid >> 7);
    int d = tid & 127;
    float v1 = out1[(size_t)an1[i] * D + d];
    float v2 = out2[(size_t)an2[i] * D + d];
    g_anch[0][i][d] = v1;
    g_anch[1][i][d] = v2;
    int q1 = __float2int_rn(fminf(fmaxf(v1 * SCALE, -127.f), 127.f)) & 255;
    int q2 = __float2int_rn(fminf(fmaxf(v2 * SCALE, -127.f), 127.f)) & 255;
    __shared__ unsigned char b1[2][D], b2[2][D];
    int h = tid >> 7;
    b1[h][d] = (unsigned char)q1;
    b2[h][d] = (unsigned char)q2;
    __syncthreads();
    if (d < D / 4) {
        g_anchq[0][i][d] = ((const uint*)b1[h])[d];
        g_anchq[1][i][d] = ((const uint*)b2[h])[d];
    }
    float x = fabsf(v1 - v2);
    #pragma unroll
    for (int off = 16; off; off >>= 1) x += __shfl_down_sync(0xffffffffu, x, off);
    __shared__ float ws[8];
    if ((tid & 31) == 0) ws[tid >> 5] = x;
    __syncthreads();
    if (d == 0) g_Dm[i] = ws[4 * h] + ws[4 * h + 1] + ws[4 * h + 2] + ws[4 * h + 3] + GAMMA;
}

// ---------------------------------------------------------------------------
// int8 SAD distances + per-chunk top-8 selection.
// Grid (64 tiles, 20 chunks, 2 sides), 512 threads, 2 CTAs/SM.
// Thread = 8 anchors x 4 consecutive rows (1 LDG.128 per dim-group j).
// ---------------------------------------------------------------------------
__global__ void __launch_bounds__(512, 2) k_dist() {
    int tile  = blockIdx.x;
    int chunk = blockIdx.y;
    int side  = blockIdx.z;
    int tid = threadIdx.x;
    int half = tid >> 8;          // 0: anchors 0-7, 1: anchors 8-15
    int pos  = tid & 255;

    __shared__ __align__(16) uint sh_aq[D / 4][TA];  // [j][t]: 2 KB
    __shared__ __align__(16) int sh_dist[TA][CROWS]; // 64 KB packed dists

    if (tid < (D / 4) * TA) {
        int j = tid >> 4, t = tid & 15;
        sh_aq[j][t] = g_anchq[side][tile * TA + t][j];
    }
    __syncthreads();

    uint acc[8][4];
    #pragma unroll
    for (int t = 0; t < 8; t++)
        #pragma unroll
        for (int r = 0; r < 4; r++) acc[t][r] = 0;

    const int p4 = 4 * pos;       // local rows p4..p4+3
    const uint* __restrict__ qp = &g_qT[side][0][0] + chunk * CROWS + p4;
    const int ta0 = half * 8;

    #pragma unroll 2
    for (int j = 0; j < D / 4; j++) {
        uint4 bv = *(const uint4*)(qp + (size_t)j * NPAD);    // rows p4..p4+3
        uint4 aL = *(const uint4*)&sh_aq[j][ta0];             // anchors ta0..+3
        uint4 aH = *(const uint4*)&sh_aq[j][ta0 + 4];         // anchors ta0+4..+7
        sad4(acc[0][0], aL.x, bv.x); sad4(acc[0][1], aL.x, bv.y);
        sad4(acc[0][2], aL.x, bv.z); sad4(acc[0][3], aL.x, bv.w);
        sad4(acc[1][0], aL.y, bv.x); sad4(acc[1][1], aL.y, bv.y);
        sad4(acc[1][2], aL.y, bv.z); sad4(acc[1][3], aL.y, bv.w);
        sad4(acc[2][0], aL.z, bv.x); sad4(acc[2][1], aL.z, bv.y);
        sad4(acc[2][2], aL.z, bv.z); sad4(acc[2][3], aL.z, bv.w);
        sad4(acc[3][0], aL.w, bv.x); sad4(acc[3][1], aL.w, bv.y);
        sad4(acc[3][2], aL.w, bv.z); sad4(acc[3][3], aL.w, bv.w);
        sad4(acc[4][0], aH.x, bv.x); sad4(acc[4][1], aH.x, bv.y);
        sad4(acc[4][2], aH.x, bv.z); sad4(acc[4][3], aH.x, bv.w);
        sad4(acc[5][0], aH.y, bv.x); sad4(acc[5][1], aH.y, bv.y);
        sad4(acc[5][2], aH.y, bv.z); sad4(acc[5][3], aH.y, bv.w);
        sad4(acc[6][0], aH.z, bv.x); sad4(acc[6][1], aH.z, bv.y);
        sad4(acc[6][2], aH.z, bv.z); sad4(acc[6][3], aH.z, bv.w);
        sad4(acc[7][0], aH.w, bv.x); sad4(acc[7][1], aH.w, bv.y);
        sad4(acc[7][2], aH.w, bv.z); sad4(acc[7][3], aH.w, bv.w);
    }

    // Store packed (sad<<10 | idx) as int4; invalid rows -> INT_MAX.
    const int nb = chunk * CROWS;
    #pragma unroll
    for (int t = 0; t < 8; t++) {
        int4 v;
        v.x = (nb + p4     < NROWS) ? (int)((acc[t][0] << 10) | (uint)(p4))     : 0x7fffffff;
        v.y = (nb + p4 + 1 < NROWS) ? (int)((acc[t][1] << 10) | (uint)(p4 + 1)) : 0x7fffffff;
        v.z = (nb + p4 + 2 < NROWS) ? (int)((acc[t][2] << 10) | (uint)(p4 + 2)) : 0x7fffffff;
        v.w = (nb + p4 + 3 < NROWS) ? (int)((acc[t][3] << 10) | (uint)(p4 + 3)) : 0x7fffffff;
        *(int4*)&sh_dist[ta0 + t][p4] = v;
    }
    __syncthreads();

    // All 16 warps: top-8 of anchor w via vectorized scan + REDUX.MIN.
    int w = tid >> 5, lane = tid & 31;
    int* row = sh_dist[w];
    int aglob = tile * TA + w;
    #pragma unroll 1
    for (int it = 0; it < KSEL; it++) {
        int m = 0x7fffffff;
        #pragma unroll
        for (int k = 0; k < 8; k++) {
            int4 v = *(const int4*)&row[4 * lane + 128 * k];
            m = min(m, min(min(v.x, v.y), min(v.z, v.w)));
        }
        m = (int)__reduce_min_sync(0xffffffffu, (uint)m);
        int idx = m & 1023;
        if (lane == 0)
            g_candi[side][aglob][chunk * KSEL + it] = chunk * CROWS + idx;
        if (((idx >> 2) & 31) == lane) row[idx] = 0x7fffffff;
        __syncwarp();
    }
}

// ---------------------------------------------------------------------------
// Exact fp32 repair: one THREAD per candidate (high MLP), then warp-0 top-10.
// ---------------------------------------------------------------------------
#define NCAND (NCHUNK * KSEL)   // 160
__global__ void __launch_bounds__(256) k_exact(const float* __restrict__ out1,
                                               const float* __restrict__ out2) {
    int a = blockIdx.x;               // 0..2047
    int side = a >> 10, ai = a & (NA - 1);
    int tid = threadIdx.x, lane = tid & 31;
    __shared__ __align__(16) float4 sh_a4[D / 4];
    __shared__ float sh_dv[NCAND];

    if (tid < D / 4) sh_a4[tid] = ((const float4*)g_anch[side][ai])[tid];
    __syncthreads();

    if (tid < NCAND) {
        int ix = g_candi[side][ai][tid];
        const float* db = side ? out1 : out2;
        const float4* rp = (const float4*)(db + (size_t)ix * D);
        float s0 = 0.f, s1 = 0.f, s2 = 0.f, s3 = 0.f;
        #pragma unroll 8
        for (int j = 0; j < D / 4; j++) {
            float4 bv = rp[j];
            float4 av = sh_a4[j];
            s0 += fabsf(av.x - bv.x);
            s1 += fabsf(av.y - bv.y);
            s2 += fabsf(av.z - bv.z);
            s3 += fabsf(av.w - bv.w);
        }
        sh_dv[tid] = (s0 + s1) + (s2 + s3);
    }
    __syncthreads();

    if (tid < 32) {
        // lane holds 5 values (stride 32); nonneg floats order as uint bits.
        float v[5];
        #pragma unroll
        for (int k = 0; k < 5; k++) v[k] = sh_dv[lane + 32 * k];
        const float INF = __int_as_float(0x7f800000);
        float Dm = g_Dm[ai];
        float loss = 0.0f;
        #pragma unroll 1
        for (int it = 0; it < KTOP; it++) {
            uint mb = 0xffffffffu;
            #pragma unroll
            for (int k = 0; k < 5; k++) mb = min(mb, __float_as_uint(v[k]));
            mb = __reduce_min_sync(0xffffffffu, mb);
            float m = __uint_as_float(mb);
            loss += fmaxf(0.0f, Dm - m);
            // remove exactly one copy of m (ballot-elected leader lane)
            bool have = (v[0] == m) | (v[1] == m) | (v[2] == m) |
                        (v[3] == m) | (v[4] == m);
            uint msk = __ballot_sync(0xffffffffu, have);
            if (lane == (int)(__ffs(msk) - 1)) {
                if      (v[0] == m) v[0] = INF;
                else if (v[1] == m) v[1] = INF;
                else if (v[2] == m) v[2] = INF;
                else if (v[3] == m) v[3] = INF;
                else                v[4] = INF;
            }
        }
        if (lane == 0) g_partial[a] = loss;
    }
}

// ---------------------------------------------------------------------------
// Deterministic final reduction: 2048 partials -> scalar / (A*K)
// ---------------------------------------------------------------------------
__global__ void k_final(float* __restrict__ out) {
    __shared__ float s[256];
    int tid = threadIdx.x;
    float v = 0.0f;
    for (int j = tid; j < 2 * NA; j += 256) v += g_partial[j];
    s[tid] = v;
    __syncthreads();
    for (int st = 128; st; st >>= 1) {
        if (tid < st) s[tid] += s[tid + st];
        __syncthreads();
    }
    if (tid == 0) out[0] = s[0] / (float)(NA * KTOP);
}

// ---------------------------------------------------------------------------
extern "C" void kernel_launch(void* const* d_in, const int* in_sizes, int n_in,
                              void* d_out, int out_size) {
    const float* out1 = (const float*)d_in[0];
    const float* out2 = (const float*)d_in[1];
    const int*   an1  = (const int*)d_in[2];
    const int*   an2  = (const int*)d_in[3];
    float* out = (float*)d_out;

    k_prep<<<2 * QB + NA / 2, 256>>>(out1, out2, an1, an2);
    k_dist<<<dim3(NA / TA, NCHUNK, 2), 512>>>();
    k_exact<<<2 * NA, 256>>>(out1, out2);
    k_final<<<1, 256>>>(out);
}

// round 8
// speedup vs baseline: 1.3983x; 1.3983x over previous
#include <cuda_runtime.h>
#include <cstdint>

#define D       128
#define NROWS   20000
#define NPAD    20480
#define NA      1024
#define TA      8         // anchors per CTA (16 spilled regs — reverted)
#define CROWS   1024
#define NCHUNK  20
#define KSEL    8
#define KTOP    10
#define GAMMA   1.0f
#define SCALE   25.4f     // int8 quant scale, selection-only
#define QB      79        // quant row-blocks (79*256 >= 20000)

typedef unsigned int uint;

// Static device scratch (allocation-free rule: __device__ globals only)
__device__ __align__(16) uint g_qT[2][D / 4][NPAD];     // transposed packed DB
__device__ __align__(16) uint g_anchq[2][NA][D / 4];    // packed quantized anchors
__device__ __align__(16) float g_anch[2][NA][D];        // fp32 anchors
__device__ float g_Dm[NA];                              // positive dist + gamma
__device__ int   g_candi[2][NA][NCHUNK * KSEL];         // candidate row indices
__device__ float g_partial[2 * NA];                     // per-anchor loss

// Fused SAD-accumulate: acc += sum_bytes(|s8(a) - s8(b)|)  (single SASS op)
__device__ __forceinline__ void sad4(uint& acc, uint a, uint b) {
    asm("vabsdiff4.u32.s32.s32.add %0, %1, %2, %0;" : "+r"(acc) : "r"(a), "r"(b));
}

__device__ __forceinline__ uint quant_pack4(float4 f) {
    int x = __float2int_rn(fminf(fmaxf(f.x * SCALE, -127.f), 127.f));
    int y = __float2int_rn(fminf(fmaxf(f.y * SCALE, -127.f), 127.f));
    int z = __float2int_rn(fminf(fmaxf(f.z * SCALE, -127.f), 127.f));
    int w = __float2int_rn(fminf(fmaxf(f.w * SCALE, -127.f), 127.f));
    return (uint)(x & 255) | ((uint)(y & 255) << 8) |
           ((uint)(z & 255) << 16) | ((uint)(w & 255) << 24);
}

// ---------------------------------------------------------------------------
// Prep: quantize+transpose DBs (blocks 0..2*QB-1) and gather anchors
// (blocks 2*QB.., 2 anchors per block).
// ---------------------------------------------------------------------------
__global__ void k_prep(const float* __restrict__ out1,
                       const float* __restrict__ out2,
                       const int* __restrict__ an1,
                       const int* __restrict__ an2) {
    int b = blockIdx.x;
    int tid = threadIdx.x;
    if (b < 2 * QB) {
        int side = (b >= QB);
        const float* src = side ? out1 : out2;
        int row = (side ? b - QB : b) * 256 + tid;
        if (row >= NROWS) return;
        const float4* s = (const float4*)(src + (size_t)row * D);
        #pragma unroll
        for (int j = 0; j < D / 4; j++)
            g_qT[side][j][row] = quant_pack4(s[j]);
        return;
    }
    // gather: 2 anchors per block, 128 threads each
    int i = (b - 2 * QB) * 2 + (tid >> 7);
    int d = tid & 127;
    float v1 = out1[(size_t)an1[i] * D + d];
    float v2 = out2[(size_t)an2[i] * D + d];
    g_anch[0][i][d] = v1;
    g_anch[1][i][d] = v2;
    int q1 = __float2int_rn(fminf(fmaxf(v1 * SCALE, -127.f), 127.f)) & 255;
    int q2 = __float2int_rn(fminf(fmaxf(v2 * SCALE, -127.f), 127.f)) & 255;
    __shared__ unsigned char b1[2][D], b2[2][D];
    int h = tid >> 7;
    b1[h][d] = (unsigned char)q1;
    b2[h][d] = (unsigned char)q2;
    __syncthreads();
    if (d < D / 4) {
        g_anchq[0][i][d] = ((const uint*)b1[h])[d];
        g_anchq[1][i][d] = ((const uint*)b2[h])[d];
    }
    float x = fabsf(v1 - v2);
    #pragma unroll
    for (int off = 16; off; off >>= 1) x += __shfl_down_sync(0xffffffffu, x, off);
    __shared__ float ws[8];
    if ((tid & 31) == 0) ws[tid >> 5] = x;
    __syncthreads();
    if (d == 0) g_Dm[i] = ws[4 * h] + ws[4 * h + 1] + ws[4 * h + 2] + ws[4 * h + 3] + GAMMA;
}

// ---------------------------------------------------------------------------
// int8 SAD distances + per-chunk top-8 selection.
// Grid (128 tiles, 20 chunks, 2 sides), 512 threads, 2 CTAs/SM.
// Thread = 4 anchors x 4 consecutive rows (1 LDG.128 per dim-group j).
// ---------------------------------------------------------------------------
__global__ void __launch_bounds__(512, 2) k_dist() {
    int tile  = blockIdx.x;
    int chunk = blockIdx.y;
    int side  = blockIdx.z;
    int tid = threadIdx.x;
    int half = tid >> 8;          // 0: anchors 0-3, 1: anchors 4-7
    int pos  = tid & 255;

    __shared__ __align__(16) uint sh_aq[D / 4][TA];  // [j][t]: 1 KB
    __shared__ __align__(16) int sh_dist[TA][CROWS]; // 32 KB packed dists

    if (tid < (D / 4) * TA) {
        int j = tid >> 3, t = tid & 7;
        sh_aq[j][t] = g_anchq[side][tile * TA + t][j];
    }
    __syncthreads();

    uint acc[4][4];
    #pragma unroll
    for (int t = 0; t < 4; t++)
        #pragma unroll
        for (int r = 0; r < 4; r++) acc[t][r] = 0;

    const int p4 = 4 * pos;       // local rows p4..p4+3 (one LDG.128)
    const uint* __restrict__ qp = &g_qT[side][0][0] + chunk * CROWS + p4;
    const int ta0 = half * 4;

    #pragma unroll 2
    for (int j = 0; j < D / 4; j++) {
        uint4 bv = *(const uint4*)(qp + (size_t)j * NPAD);  // rows p4..p4+3
        uint4 av = *(const uint4*)&sh_aq[j][ta0];           // anchors ta0..+3
        sad4(acc[0][0], av.x, bv.x); sad4(acc[0][1], av.x, bv.y);
        sad4(acc[0][2], av.x, bv.z); sad4(acc[0][3], av.x, bv.w);
        sad4(acc[1][0], av.y, bv.x); sad4(acc[1][1], av.y, bv.y);
        sad4(acc[1][2], av.y, bv.z); sad4(acc[1][3], av.y, bv.w);
        sad4(acc[2][0], av.z, bv.x); sad4(acc[2][1], av.z, bv.y);
        sad4(acc[2][2], av.z, bv.z); sad4(acc[2][3], av.z, bv.w);
        sad4(acc[3][0], av.w, bv.x); sad4(acc[3][1], av.w, bv.y);
        sad4(acc[3][2], av.w, bv.z); sad4(acc[3][3], av.w, bv.w);
    }

    // Store packed (sad<<10 | idx) as int4; invalid rows -> INT_MAX.
    const int nb = chunk * CROWS;
    #pragma unroll
    for (int t = 0; t < 4; t++) {
        int4 v;
        v.x = (nb + p4     < NROWS) ? (int)((acc[t][0] << 10) | (uint)(p4))     : 0x7fffffff;
        v.y = (nb + p4 + 1 < NROWS) ? (int)((acc[t][1] << 10) | (uint)(p4 + 1)) : 0x7fffffff;
        v.z = (nb + p4 + 2 < NROWS) ? (int)((acc[t][2] << 10) | (uint)(p4 + 2)) : 0x7fffffff;
        v.w = (nb + p4 + 3 < NROWS) ? (int)((acc[t][3] << 10) | (uint)(p4 + 3)) : 0x7fffffff;
        *(int4*)&sh_dist[ta0 + t][p4] = v;
    }
    __syncthreads();

    // Warps 0-7: top-8 of anchor w via vectorized scan + REDUX.MIN.
    int w = tid >> 5, lane = tid & 31;
    if (w < TA) {
        int* row = sh_dist[w];
        int aglob = tile * TA + w;
        #pragma unroll 1
        for (int it = 0; it < KSEL; it++) {
            int m = 0x7fffffff;
            #pragma unroll
            for (int k = 0; k < 8; k++) {
                int4 v = *(const int4*)&row[4 * lane + 128 * k];
                m = min(m, min(min(v.x, v.y), min(v.z, v.w)));
            }
            m = (int)__reduce_min_sync(0xffffffffu, (uint)m);
            int idx = m & 1023;
            if (lane == 0)
                g_candi[side][aglob][chunk * KSEL + it] = chunk * CROWS + idx;
            if (((idx >> 2) & 31) == lane) row[idx] = 0x7fffffff;
            __syncwarp();
        }
    }
}

// ---------------------------------------------------------------------------
// Exact fp32 repair: one THREAD per candidate (high MLP), then warp-0 top-10.
// ---------------------------------------------------------------------------
#define NCAND (NCHUNK * KSEL)   // 160
__global__ void __launch_bounds__(256) k_exact(const float* __restrict__ out1,
                                               const float* __restrict__ out2) {
    int a = blockIdx.x;               // 0..2047
    int side = a >> 10, ai = a & (NA - 1);
    int tid = threadIdx.x, lane = tid & 31;
    __shared__ __align__(16) float4 sh_a4[D / 4];
    __shared__ float sh_dv[NCAND];

    if (tid < D / 4) sh_a4[tid] = ((const float4*)g_anch[side][ai])[tid];
    __syncthreads();

    if (tid < NCAND) {
        int ix = g_candi[side][ai][tid];
        const float* db = side ? out1 : out2;
        const float4* rp = (const float4*)(db + (size_t)ix * D);
        float s0 = 0.f, s1 = 0.f, s2 = 0.f, s3 = 0.f;
        #pragma unroll 8
        for (int j = 0; j < D / 4; j++) {
            float4 bv = rp[j];
            float4 av = sh_a4[j];
            s0 += fabsf(av.x - bv.x);
            s1 += fabsf(av.y - bv.y);
            s2 += fabsf(av.z - bv.z);
            s3 += fabsf(av.w - bv.w);
        }
        sh_dv[tid] = (s0 + s1) + (s2 + s3);
    }
    __syncthreads();

    if (tid < 32) {
        // lane holds 5 values (stride 32); nonneg floats order as uint bits.
        float v[5];
        #pragma unroll
        for (int k = 0; k < 5; k++) v[k] = sh_dv[lane + 32 * k];
        const float INF = __int_as_float(0x7f800000);
        float Dm = g_Dm[ai];
        float loss = 0.0f;
        #pragma unroll 1
        for (int it = 0; it < KTOP; it++) {
            uint mb = 0xffffffffu;
            #pragma unroll
            for (int k = 0; k < 5; k++) mb = min(mb, __float_as_uint(v[k]));
            mb = __reduce_min_sync(0xffffffffu, mb);
            float m = __uint_as_float(mb);
            loss += fmaxf(0.0f, Dm - m);
            // remove exactly one copy of m (ballot-elected leader lane)
            bool have = (v[0] == m) | (v[1] == m) | (v[2] == m) |
                        (v[3] == m) | (v[4] == m);
            uint msk = __ballot_sync(0xffffffffu, have);
            if (lane == (int)(__ffs(msk) - 1)) {
                if      (v[0] == m) v[0] = INF;
                else if (v[1] == m) v[1] = INF;
                else if (v[2] == m) v[2] = INF;
                else if (v[3] == m) v[3] = INF;
                else                v[4] = INF;
            }
        }
        if (lane == 0) g_partial[a] = loss;
    }
}

// ---------------------------------------------------------------------------
// Deterministic final reduction: 2048 partials -> scalar / (A*K)
// ---------------------------------------------------------------------------
__global__ void k_final(float* __restrict__ out) {
    __shared__ float s[512];
    int tid = threadIdx.x;   // 1024 threads; 512 float4 elements total
    float v = 0.0f;
    if (tid < 512) {
        float4 p = ((const float4*)g_partial)[tid];
        v = (p.x + p.y) + (p.z + p.w);
        s[tid] = v;
    }
    __syncthreads();
    for (int st = 256; st; st >>= 1) {
        if (tid < st) s[tid] += s[tid + st];
        __syncthreads();
    }
    if (tid == 0) out[0] = s[0] / (float)(NA * KTOP);
}

// ---------------------------------------------------------------------------
extern "C" void kernel_launch(void* const* d_in, const int* in_sizes, int n_in,
                              void* d_out, int out_size) {
    const float* out1 = (const float*)d_in[0];
    const float* out2 = (const float*)d_in[1];
    const int*   an1  = (const int*)d_in[2];
    const int*   an2  = (const int*)d_in[3];
    float* out = (float*)d_out;

    k_prep<<<2 * QB + NA / 2, 256>>>(out1, out2, an1, an2);
    k_dist<<<dim3(NA / TA, NCHUNK, 2), 512>>>();
    k_exact<<<2 * NA, 256>>>(out1, out2);
    k_final<<<1, 1024>>>(out);
}

// round 9
// speedup vs baseline: 1.5763x; 1.1273x over previous
#include <cuda_runtime.h>
#include <cstdint>

#define D       128
#define NROWS   20000
#define NPAD    20480
#define NA      1024
#define TA      8         // anchors per CTA
#define CROWS   1024
#define NCHUNK  20
#define KSEL    8
#define KTOP    10
#define GAMMA   1.0f
#define SCALE   25.4f     // int8 quant scale, selection-only
#define QB      79        // quant row-blocks (79*256 >= 20000)

typedef unsigned int uint;

// Static device scratch (allocation-free rule: __device__ globals only)
__device__ __align__(16) uint g_qT[2][D / 4][NPAD];     // transposed packed DB
__device__ __align__(16) uint g_anchq[2][NA][D / 4];    // packed quantized anchors
__device__ __align__(16) float g_anch[2][NA][D];        // fp32 anchors
__device__ float g_Dm[NA];                              // positive dist + gamma
__device__ int   g_candi[2][NA][NCHUNK * KSEL];         // candidate row indices
__device__ float g_partial[2 * NA];                     // per-anchor loss

// Fused SAD-accumulate: acc += sum_bytes(|s8(a) - s8(b)|)  (single SASS op)
__device__ __forceinline__ void sad4(uint& acc, uint a, uint b) {
    asm("vabsdiff4.u32.s32.s32.add %0, %1, %2, %0;" : "+r"(acc) : "r"(a), "r"(b));
}

__device__ __forceinline__ uint quant_pack4(float4 f) {
    int x = __float2int_rn(fminf(fmaxf(f.x * SCALE, -127.f), 127.f));
    int y = __float2int_rn(fminf(fmaxf(f.y * SCALE, -127.f), 127.f));
    int z = __float2int_rn(fminf(fmaxf(f.z * SCALE, -127.f), 127.f));
    int w = __float2int_rn(fminf(fmaxf(f.w * SCALE, -127.f), 127.f));
    return (uint)(x & 255) | ((uint)(y & 255) << 8) |
           ((uint)(z & 255) << 16) | ((uint)(w & 255) << 24);
}

// ---------------------------------------------------------------------------
// Prep: quantize+transpose DBs (blocks 0..2*QB-1) and gather anchors
// (blocks 2*QB.., 2 anchors per block).
// ---------------------------------------------------------------------------
__global__ void k_prep(const float* __restrict__ out1,
                       const float* __restrict__ out2,
                       const int* __restrict__ an1,
                       const int* __restrict__ an2) {
    int b = blockIdx.x;
    int tid = threadIdx.x;
    if (b < 2 * QB) {
        int side = (b >= QB);
        const float* src = side ? out1 : out2;
        int row = (side ? b - QB : b) * 256 + tid;
        if (row >= NROWS) return;
        const float4* s = (const float4*)(src + (size_t)row * D);
        #pragma unroll
        for (int j = 0; j < D / 4; j++)
            g_qT[side][j][row] = quant_pack4(s[j]);
        return;
    }
    // gather: 2 anchors per block, 128 threads each
    int i = (b - 2 * QB) * 2 + (tid >> 7);
    int d = tid & 127;
    float v1 = out1[(size_t)an1[i] * D + d];
    float v2 = out2[(size_t)an2[i] * D + d];
    g_anch[0][i][d] = v1;
    g_anch[1][i][d] = v2;
    int q1 = __float2int_rn(fminf(fmaxf(v1 * SCALE, -127.f), 127.f)) & 255;
    int q2 = __float2int_rn(fminf(fmaxf(v2 * SCALE, -127.f), 127.f)) & 255;
    __shared__ unsigned char b1[2][D], b2[2][D];
    int h = tid >> 7;
    b1[h][d] = (unsigned char)q1;
    b2[h][d] = (unsigned char)q2;
    __syncthreads();
    if (d < D / 4) {
        g_anchq[0][i][d] = ((const uint*)b1[h])[d];
        g_anchq[1][i][d] = ((const uint*)b2[h])[d];
    }
    float x = fabsf(v1 - v2);
    #pragma unroll
    for (int off = 16; off; off >>= 1) x += __shfl_down_sync(0xffffffffu, x, off);
    __shared__ float ws[8];
    if ((tid & 31) == 0) ws[tid >> 5] = x;
    __syncthreads();
    if (d == 0) g_Dm[i] = ws[4 * h] + ws[4 * h + 1] + ws[4 * h + 2] + ws[4 * h + 3] + GAMMA;
}

// ---------------------------------------------------------------------------
// int8 SAD distances + per-chunk top-8 selection.  (round-6 proven: 107us)
// Grid (128 tiles, 20 chunks, 2 sides), 512 threads.
// Thread = 4 anchors x 4 rows {2p, 2p+1, 2p+512, 2p+513} (2x LDG.64 per j).
// Fully-unrolled mainloop => high LDG MLP (load-bearing for latency hiding).
// ---------------------------------------------------------------------------
__global__ void __launch_bounds__(512, 2) k_dist() {
    int tile  = blockIdx.x;
    int chunk = blockIdx.y;
    int side  = blockIdx.z;
    int tid = threadIdx.x;
    int half = tid >> 8;          // anchor group: 0 -> anchors 0-3, 1 -> 4-7
    int pos  = tid & 255;

    __shared__ __align__(16) uint sh_aq[TA][D / 4];  // 1 KB
    __shared__ __align__(16) int sh_dist[TA][CROWS]; // 32 KB packed dists

    if (tid < TA * (D / 4)) {
        int t = tid >> 5, j = tid & 31;
        sh_aq[t][j] = g_anchq[side][tile * TA + t][j];
    }
    __syncthreads();

    uint acc[4][4];
    #pragma unroll
    for (int t = 0; t < 4; t++)
        #pragma unroll
        for (int r = 0; r < 4; r++) acc[t][r] = 0;

    const int p2 = 2 * pos;       // local rows p2, p2+1, p2+512, p2+513
    const uint* __restrict__ qp = &g_qT[side][0][0] + chunk * CROWS + p2;
    const int ta0 = half * 4;

    #pragma unroll
    for (int jb = 0; jb < 8; jb++) {
        uint4 a0 = *(const uint4*)&sh_aq[ta0 + 0][4 * jb];
        uint4 a1 = *(const uint4*)&sh_aq[ta0 + 1][4 * jb];
        uint4 a2 = *(const uint4*)&sh_aq[ta0 + 2][4 * jb];
        uint4 a3 = *(const uint4*)&sh_aq[ta0 + 3][4 * jb];
        #pragma unroll
        for (int jj = 0; jj < 4; jj++) {
            int j = 4 * jb + jj;
            uint2 bA = *(const uint2*)(qp + (size_t)j * NPAD);        // rows p2,p2+1
            uint2 bB = *(const uint2*)(qp + (size_t)j * NPAD + 512);  // +512,+513
            uint av0 = jj == 0 ? a0.x : jj == 1 ? a0.y : jj == 2 ? a0.z : a0.w;
            uint av1 = jj == 0 ? a1.x : jj == 1 ? a1.y : jj == 2 ? a1.z : a1.w;
            uint av2 = jj == 0 ? a2.x : jj == 1 ? a2.y : jj == 2 ? a2.z : a2.w;
            uint av3 = jj == 0 ? a3.x : jj == 1 ? a3.y : jj == 2 ? a3.z : a3.w;
            sad4(acc[0][0], av0, bA.x);
            sad4(acc[0][1], av0, bA.y);
            sad4(acc[0][2], av0, bB.x);
            sad4(acc[0][3], av0, bB.y);
            sad4(acc[1][0], av1, bA.x);
            sad4(acc[1][1], av1, bA.y);
            sad4(acc[1][2], av1, bB.x);
            sad4(acc[1][3], av1, bB.y);
            sad4(acc[2][0], av2, bA.x);
            sad4(acc[2][1], av2, bA.y);
            sad4(acc[2][2], av2, bB.x);
            sad4(acc[2][3], av2, bB.y);
            sad4(acc[3][0], av3, bA.x);
            sad4(acc[3][1], av3, bA.y);
            sad4(acc[3][2], av3, bB.x);
            sad4(acc[3][3], av3, bB.y);
        }
    }

    // Store packed (sad<<10 | idx); invalid rows -> INT_MAX.
    const int nb = chunk * CROWS;
    #pragma unroll
    for (int r = 0; r < 4; r++) {
        int idx = (r & 1) + ((r >> 1) << 9) + p2;   // p2, p2+1, p2+512, p2+513
        bool valid = (nb + idx) < NROWS;
        #pragma unroll
        for (int t = 0; t < 4; t++) {
            int v = valid ? (int)((acc[t][r] << 10) | (uint)idx) : 0x7fffffff;
            sh_dist[ta0 + t][idx] = v;
        }
    }
    __syncthreads();

    // Warps 0-7: top-8 of anchor w via vectorized scan + REDUX.MIN.
    int w = tid >> 5, lane = tid & 31;
    if (w < TA) {
        int* row = sh_dist[w];
        int aglob = tile * TA + w;
        #pragma unroll 1
        for (int it = 0; it < KSEL; it++) {
            int m = 0x7fffffff;
            #pragma unroll
            for (int k = 0; k < 8; k++) {
                int4 v = *(const int4*)&row[4 * lane + 128 * k];
                m = min(m, min(min(v.x, v.y), min(v.z, v.w)));
            }
            m = (int)__reduce_min_sync(0xffffffffu, (uint)m);
            int idx = m & 1023;
            if (lane == 0)
                g_candi[side][aglob][chunk * KSEL + it] = chunk * CROWS + idx;
            if (((idx >> 2) & 31) == lane) row[idx] = 0x7fffffff;
            __syncwarp();
        }
    }
}

// ---------------------------------------------------------------------------
// Exact fp32 repair: one THREAD per candidate (high MLP), then warp-0 top-10.
// ---------------------------------------------------------------------------
#define NCAND (NCHUNK * KSEL)   // 160
__global__ void __launch_bounds__(256) k_exact(const float* __restrict__ out1,
                                               const float* __restrict__ out2) {
    int a = blockIdx.x;               // 0..2047
    int side = a >> 10, ai = a & (NA - 1);
    int tid = threadIdx.x, lane = tid & 31;
    __shared__ __align__(16) float4 sh_a4[D / 4];
    __shared__ float sh_dv[NCAND];

    if (tid < D / 4) sh_a4[tid] = ((const float4*)g_anch[side][ai])[tid];
    __syncthreads();

    if (tid < NCAND) {
        int ix = g_candi[side][ai][tid];
        const float* db = side ? out1 : out2;
        const float4* rp = (const float4*)(db + (size_t)ix * D);
        float s0 = 0.f, s1 = 0.f, s2 = 0.f, s3 = 0.f;
        #pragma unroll 8
        for (int j = 0; j < D / 4; j++) {
            float4 bv = rp[j];
            float4 av = sh_a4[j];
            s0 += fabsf(av.x - bv.x);
            s1 += fabsf(av.y - bv.y);
            s2 += fabsf(av.z - bv.z);
            s3 += fabsf(av.w - bv.w);
        }
        sh_dv[tid] = (s0 + s1) + (s2 + s3);
    }
    __syncthreads();

    if (tid < 32) {
        // lane holds 5 values (stride 32); nonneg floats order as uint bits.
        float v[5];
        #pragma unroll
        for (int k = 0; k < 5; k++) v[k] = sh_dv[lane + 32 * k];
        const float INF = __int_as_float(0x7f800000);
        float Dm = g_Dm[ai];
        float loss = 0.0f;
        #pragma unroll 1
        for (int it = 0; it < KTOP; it++) {
            uint mb = 0xffffffffu;
            #pragma unroll
            for (int k = 0; k < 5; k++) mb = min(mb, __float_as_uint(v[k]));
            mb = __reduce_min_sync(0xffffffffu, mb);
            float m = __uint_as_float(mb);
            loss += fmaxf(0.0f, Dm - m);
            // remove exactly one copy of m (ballot-elected leader lane)
            bool have = (v[0] == m) | (v[1] == m) | (v[2] == m) |
                        (v[3] == m) | (v[4] == m);
            uint msk = __ballot_sync(0xffffffffu, have);
            if (lane == (int)(__ffs(msk) - 1)) {
                if      (v[0] == m) v[0] = INF;
                else if (v[1] == m) v[1] = INF;
                else if (v[2] == m) v[2] = INF;
                else if (v[3] == m) v[3] = INF;
                else                v[4] = INF;
            }
        }
        if (lane == 0) g_partial[a] = loss;
    }
}

// ---------------------------------------------------------------------------
// Deterministic final reduction: 2048 partials -> scalar / (A*K)
// ---------------------------------------------------------------------------
__global__ void k_final(float* __restrict__ out) {
    __shared__ float s[512];
    int tid = threadIdx.x;   // 1024 threads; 512 float4 elements total
    float v = 0.0f;
    if (tid < 512) {
        float4 p = ((const float4*)g_partial)[tid];
        v = (p.x + p.y) + (p.z + p.w);
        s[tid] = v;
    }
    __syncthreads();
    for (int st = 256; st; st >>= 1) {
        if (tid < st) s[tid] += s[tid + st];
        __syncthreads();
    }
    if (tid == 0) out[0] = s[0] / (float)(NA * KTOP);
}

// ---------------------------------------------------------------------------
extern "C" void kernel_launch(void* const* d_in, const int* in_sizes, int n_in,
                              void* d_out, int out_size) {
    const float* out1 = (const float*)d_in[0];
    const float* out2 = (const float*)d_in[1];
    const int*   an1  = (const int*)d_in[2];
    const int*   an2  = (const int*)d_in[3];
    float* out = (float*)d_out;

    k_prep<<<2 * QB + NA / 2, 256>>>(out1, out2, an1, an2);
    k_dist<<<dim3(NA / TA, NCHUNK, 2), 512>>>();
    k_exact<<<2 * NA, 256>>>(out1, out2);
    k_final<<<1, 1024>>>(out);
}